// round 14
// baseline (speedup 1.0000x reference)
#include <cuda_runtime.h>
#include <cuda_bf16.h>
#include <cstdint>
#include <cstddef>

#define VOCAB 32000
#define EMB   32
#define REC   16
#define SEQ   256
#define BATCH 32

#define NT8 (VOCAB / 8)              // 4000 vocab n-tiles of 8 rows

// role A (sumexp): 10 slices -> 400 tiles/CTA, 50/warp
#define SLICES_A 10
#define TPC_A    (NT8 / SLICES_A)
#define TPW_A    (TPC_A / 8)

// role B (write): chunks of 32 vocab (4 n-tiles). 1000 chunks per s.
#define NCHUNKS   (VOCAB / 32)       // 1000
#define SLICES_B  25
#define CPC_B     (NCHUNKS / SLICES_B)   // 40 chunks/CTA
#define CPW_B     (CPC_B / 8)            // 5 chunks/warp

// pipelined bid layout: group g = 10 A-CTAs (s=g) + 25 B-CTAs (s=g-DELTA)
#define DELTA   8
#define GROUPS  (SEQ + DELTA)
#define GSIZE   (SLICES_A + SLICES_B)    // 35
#define TOTAL_F (GROUPS * GSIZE)

// prep kernel roles
#define VPREP_CTAS ((NT8 * 32 + 255) / 256)              // 500
#define IPROJ_CTAS ((SEQ * BATCH * REC + 255) / 256)     // 512

// Scratch (allocation-free rule: __device__ globals)
__device__ float g_hidden[SEQ * BATCH * REC];
__device__ float g_iproj [SEQ * BATCH * REC];
__device__ float g_sumexp[SEQ * BATCH];
__device__ int   g_done  [SEQ];
__device__ uint2 g_Vmma  [NT8 * 32];   // V as B-operand fragments, lane-ordered

// ---------------------------------------------------------------------------
// helpers
// ---------------------------------------------------------------------------
__device__ __forceinline__ uint32_t pk2(float a, float b) {
    __nv_bfloat162 t = __float22bfloat162_rn(make_float2(a, b));
    return *reinterpret_cast<uint32_t*>(&t);
}

// D(16x8,f32) = A(16x16,bf16,row) * B(16x8,bf16,col) + D   — base-ISA HMMA
__device__ __forceinline__ void mma16816(float* d, const uint32_t* a,
                                         uint32_t b0, uint32_t b1) {
    asm volatile(
        "mma.sync.aligned.m16n8k16.row.col.f32.bf16.bf16.f32 "
        "{%0,%1,%2,%3}, {%4,%5,%6,%7}, {%8,%9}, {%0,%1,%2,%3};"
        : "+f"(d[0]), "+f"(d[1]), "+f"(d[2]), "+f"(d[3])
        : "r"(a[0]), "r"(a[1]), "r"(a[2]), "r"(a[3]), "r"(b0), "r"(b1));
}

// ---------------------------------------------------------------------------
// Kernel 1 (fused prep): bid < VPREP_CTAS -> pack V fragments;
// else -> input projection + zero g_sumexp/g_done.
// ---------------------------------------------------------------------------
__global__ void prep_kernel(const float* __restrict__ V,
                            const int* __restrict__ tok,
                            const float* __restrict__ emb,
                            const float* __restrict__ U,
                            const float* __restrict__ b1,
                            const float* __restrict__ b2) {
    if (blockIdx.x < VPREP_CTAS) {
        int idx = blockIdx.x * blockDim.x + threadIdx.x;
        if (idx >= NT8 * 32) return;
        int tile = idx >> 5, lane = idx & 31;
        int g = lane >> 2, t = lane & 3;
        const float* r = V + (size_t)(tile * 8 + g) * REC;
        uint2 b;
        b.x = pk2(r[2 * t],     r[2 * t + 1]);
        b.y = pk2(r[2 * t + 8], r[2 * t + 9]);
        g_Vmma[idx] = b;
    } else {
        int idx = (blockIdx.x - VPREP_CTAS) * blockDim.x + threadIdx.x;
        if (idx < SEQ * BATCH) g_sumexp[idx] = 0.0f;
        if (idx < SEQ) g_done[idx] = 0;
        if (idx >= SEQ * BATCH * REC) return;
        int r  = idx & (REC - 1);
        int sb = idx >> 4;
        int t  = tok[sb];
        const float4* e = (const float4*)(emb + (size_t)t * EMB);
        const float4* u = (const float4*)(U + (size_t)r * EMB);
        float acc = b1[r] + b2[r];
#pragma unroll
        for (int q = 0; q < EMB / 4; q++) {
            float4 ev = e[q], uv = u[q];
            acc = fmaf(ev.x, uv.x, acc);
            acc = fmaf(ev.y, uv.y, acc);
            acc = fmaf(ev.z, uv.z, acc);
            acc = fmaf(ev.w, uv.w, acc);
        }
        g_iproj[idx] = acc;
    }
}

// ---------------------------------------------------------------------------
// Kernel 2: recurrence, barrier-free. 512 threads = 16 warps; warp w owns
// batches {2w, 2w+1}; lane = 16*(b&1) + r. h exchange via 16-wide shuffles.
// Per warp, global loads/stores are 128B coalesced (addr = 32w + lane).
// ---------------------------------------------------------------------------
__global__ void __launch_bounds__(512) rnn_kernel(const float* __restrict__ W,
                                                  const float* __restrict__ h0) {
    const int tid  = threadIdx.x;
    const int w    = tid >> 5, lane = tid & 31;
    const int r    = lane & 15;
    const int base = 32 * w + lane;           // == b*16 + r

    float wreg[REC];
    {
        const float4* wr = (const float4*)(W + r * REC);
        float4 a = wr[0], b = wr[1], c = wr[2], d = wr[3];
        wreg[0]=a.x; wreg[1]=a.y; wreg[2]=a.z; wreg[3]=a.w;
        wreg[4]=b.x; wreg[5]=b.y; wreg[6]=b.z; wreg[7]=b.w;
        wreg[8]=c.x; wreg[9]=c.y; wreg[10]=c.z; wreg[11]=c.w;
        wreg[12]=d.x; wreg[13]=d.y; wreg[14]=d.z; wreg[15]=d.w;
    }

    float c0 = h0[r];

    float ip[2];
    ip[0] = g_iproj[base];
    ip[1] = g_iproj[512 + base];

    for (int t = 0; t < SEQ; t++) {
        g_hidden[t * 512 + base] = c0;
        if (t < SEQ - 1) {
            float acc0 = ip[t & 1], acc1 = 0.f;
            if (t + 2 < SEQ) ip[t & 1] = g_iproj[(t + 2) * 512 + base];
#pragma unroll
            for (int j = 0; j < 8; j++) {
                float hj0 = __shfl_sync(0xffffffffu, c0, j, 16);
                float hj1 = __shfl_sync(0xffffffffu, c0, j + 8, 16);
                acc0 = fmaf(wreg[j], hj0, acc0);
                acc1 = fmaf(wreg[j + 8], hj1, acc1);
            }
            float x = acc0 + acc1;
            float e = __expf(2.0f * x);
            c0 = 1.0f - __fdividef(2.0f, e + 1.0f);
        }
    }
}

// Build A fragments (h, batch-as-M): 2 m-tiles (batch 0-15, 16-31).
__device__ __forceinline__ void make_afrags(uint32_t a[2][4], int s, int g, int t) {
    const float* hb = g_hidden + s * 512;
#pragma unroll
    for (int m = 0; m < 2; m++) {
        int r0 = m * 16 + g, r1 = m * 16 + g + 8;
        float2 x0 = *(const float2*)(hb + r0 * REC + 2 * t);
        float2 x1 = *(const float2*)(hb + r1 * REC + 2 * t);
        float2 x2 = *(const float2*)(hb + r0 * REC + 2 * t + 8);
        float2 x3 = *(const float2*)(hb + r1 * REC + 2 * t + 8);
        a[m][0] = pk2(x0.x, x0.y);
        a[m][1] = pk2(x1.x, x1.y);
        a[m][2] = pk2(x2.x, x2.y);
        a[m][3] = pk2(x3.x, x3.y);
    }
}

// ---------------------------------------------------------------------------
// Kernel 3 (FUSED, software-pipelined): group g = 10 A-CTAs for s=g followed
// by 25 B-CTAs for s=g-DELTA. B's producers are 8 groups earlier in bid
// order -> spin is short and deadlock-free; A (MUFU) and B (DRAM) coexist.
// ---------------------------------------------------------------------------
__global__ void __launch_bounds__(256) fused_kernel(float* __restrict__ out) {
    __shared__ float buf[8][32][36];
    const int grp = blockIdx.x / GSIZE;
    const int idx = blockIdx.x % GSIZE;
    const int tid = threadIdx.x;
    const int wid = tid >> 5, lane = tid & 31;
    const int g = lane >> 2, t = lane & 3;

    if (idx < SLICES_A) {
        // ---------------- sumexp role ----------------
        const int s = grp;
        if (s >= SEQ) return;
        const int slice = idx;

        uint32_t a[2][4];
        make_afrags(a, s, g, t);

        float acc[4] = {0.f, 0.f, 0.f, 0.f};
        const int tile0 = slice * TPC_A + wid * TPW_A;
        const uint2* bp = &g_Vmma[(size_t)tile0 * 32 + lane];

        for (int i = 0; i < TPW_A; i++) {
            uint2 b = bp[i * 32];
            float d0[4] = {0.f, 0.f, 0.f, 0.f};
            float d1[4] = {0.f, 0.f, 0.f, 0.f};
            mma16816(d0, a[0], b.x, b.y);
            mma16816(d1, a[1], b.x, b.y);
            acc[0] += __expf(d0[0]) + __expf(d0[1]);
            acc[1] += __expf(d0[2]) + __expf(d0[3]);
            acc[2] += __expf(d1[0]) + __expf(d1[1]);
            acc[3] += __expf(d1[2]) + __expf(d1[3]);
        }

#pragma unroll
        for (int k = 0; k < 4; k++) {
            float v = acc[k];
            v += __shfl_xor_sync(0xffffffffu, v, 1);
            v += __shfl_xor_sync(0xffffffffu, v, 2);
            acc[k] = v;
        }

        float (*red)[BATCH] = (float (*)[BATCH])buf;
        if (t == 0) {
            red[wid][g]      = acc[0];
            red[wid][g + 8]  = acc[1];
            red[wid][g + 16] = acc[2];
            red[wid][g + 24] = acc[3];
        }
        __syncthreads();
        if (tid < BATCH) {
            float tot = 0.f;
#pragma unroll
            for (int w = 0; w < 8; w++) tot += red[w][tid];
            atomicAdd(&g_sumexp[s * BATCH + tid], tot);
        }
        __syncthreads();
        if (tid == 0) {
            __threadfence();
            atomicAdd(&g_done[s], 1);
        }
    } else {
        // ---------------- write role ----------------
        const int s = grp - DELTA;
        if (s < 0 || s >= SEQ) return;
        const int slice = idx - SLICES_A;

        uint32_t a[2][4];
        make_afrags(a, s, g, t);

        if (tid == 0) {
            while (atomicAdd(&g_done[s], 0) < SLICES_A) __nanosleep(128);
        }
        __syncthreads();
        __threadfence();

        const float* se = g_sumexp + s * BATCH;
        const float nz0 = -__logf(se[g]);
        const float nz1 = -__logf(se[g + 8]);
        const float nz2 = -__logf(se[g + 16]);
        const float nz3 = -__logf(se[g + 24]);

        float* obase = out + (size_t)s * BATCH * VOCAB;
        float (*wb)[36] = buf[wid];

        const int rrow = lane >> 3;
        const int rcol = (lane & 7) * 4;

        for (int i = 0; i < CPW_B; i++) {
            const int chunk = slice * CPC_B + i * 8 + wid;
            const int v0 = chunk * 32;

#pragma unroll
            for (int jj = 0; jj < 4; jj++) {
                uint2 b = g_Vmma[(size_t)(chunk * 4 + jj) * 32 + lane];
                float d0[4] = {nz0, nz0, nz1, nz1};
                float d1[4] = {nz2, nz2, nz3, nz3};
                mma16816(d0, a[0], b.x, b.y);
                mma16816(d1, a[1], b.x, b.y);
                const int col = jj * 8 + 2 * t;
                *(float2*)&wb[g][col]      = make_float2(d0[0], d0[1]);
                *(float2*)&wb[g + 8][col]  = make_float2(d0[2], d0[3]);
                *(float2*)&wb[g + 16][col] = make_float2(d1[0], d1[1]);
                *(float2*)&wb[g + 24][col] = make_float2(d1[2], d1[3]);
            }
            __syncwarp();

#pragma unroll
            for (int it = 0; it < 8; it++) {
                const int row = it * 4 + rrow;
                float4 x = *(float4*)&wb[row][rcol];
                *(float4*)(obase + (size_t)row * VOCAB + v0 + rcol) = x;
            }
            __syncwarp();
        }
    }
}

// ---------------------------------------------------------------------------
extern "C" void kernel_launch(void* const* d_in, const int* in_sizes, int n_in,
                              void* d_out, int out_size) {
    const int*   tok = (const int*)  d_in[0];
    const float* emb = (const float*)d_in[1];
    const float* U   = (const float*)d_in[2];
    const float* W   = (const float*)d_in[3];
    const float* V   = (const float*)d_in[4];
    const float* b1  = (const float*)d_in[5];
    const float* b2  = (const float*)d_in[6];
    const float* h0  = (const float*)d_in[7];
    float* out = (float*)d_out;

    prep_kernel<<<VPREP_CTAS + IPROJ_CTAS, 256>>>(V, tok, emb, U, b1, b2);
    rnn_kernel<<<1, 512>>>(W, h0);
    fused_kernel<<<TOTAL_F, 256>>>(out);
}

// round 15
// speedup vs baseline: 1.6277x; 1.6277x over previous
#include <cuda_runtime.h>
#include <cuda_bf16.h>
#include <cstdint>
#include <cstddef>

#define VOCAB 32000
#define EMB   32
#define REC   16
#define SEQ   256
#define BATCH 32

#define NT8 (VOCAB / 8)              // 4000 vocab n-tiles of 8 rows

// role A (sumexp): 10 slices -> 400 tiles/CTA, 50/warp
#define SLICES_A 10
#define TPC_A    (NT8 / SLICES_A)
#define TPW_A    (TPC_A / 8)
#define TOTAL_A  (SLICES_A * SEQ)    // 2560 CTAs

// role B (write): chunks of 32 vocab (4 n-tiles). 1000 chunks per s.
#define NCHUNKS   (VOCAB / 32)       // 1000
#define SLICES_B  25
#define CPC_B     (NCHUNKS / SLICES_B)   // 40 chunks/CTA
#define CPW_B     (CPC_B / 8)            // 5 chunks/warp
#define TOTAL_B   (SLICES_B * SEQ)       // 6400 CTAs

// prep kernel roles
#define VPREP_CTAS ((NT8 * 32 + 255) / 256)              // 500
#define IPROJ_CTAS ((SEQ * BATCH * REC + 255) / 256)     // 512

// Scratch (allocation-free rule: __device__ globals)
__device__ float g_hidden[SEQ * BATCH * REC];
__device__ float g_iproj [SEQ * BATCH * REC];
__device__ float g_sumexp[SEQ * BATCH];
__device__ int   g_done  [SEQ];
__device__ uint2 g_Vmma  [NT8 * 32];   // V as B-operand fragments, lane-ordered

// ---------------------------------------------------------------------------
// helpers
// ---------------------------------------------------------------------------
__device__ __forceinline__ uint32_t pk2(float a, float b) {
    __nv_bfloat162 t = __float22bfloat162_rn(make_float2(a, b));
    return *reinterpret_cast<uint32_t*>(&t);
}

// D(16x8,f32) = A(16x16,bf16,row) * B(16x8,bf16,col) + D   — base-ISA HMMA
__device__ __forceinline__ void mma16816(float* d, const uint32_t* a,
                                         uint32_t b0, uint32_t b1) {
    asm volatile(
        "mma.sync.aligned.m16n8k16.row.col.f32.bf16.bf16.f32 "
        "{%0,%1,%2,%3}, {%4,%5,%6,%7}, {%8,%9}, {%0,%1,%2,%3};"
        : "+f"(d[0]), "+f"(d[1]), "+f"(d[2]), "+f"(d[3])
        : "r"(a[0]), "r"(a[1]), "r"(a[2]), "r"(a[3]), "r"(b0), "r"(b1));
}

// ---------------------------------------------------------------------------
// Kernel 1 (fused prep): bid < VPREP_CTAS -> pack V fragments;
// else -> input projection + zero g_sumexp/g_done.
// ---------------------------------------------------------------------------
__global__ void prep_kernel(const float* __restrict__ V,
                            const int* __restrict__ tok,
                            const float* __restrict__ emb,
                            const float* __restrict__ U,
                            const float* __restrict__ b1,
                            const float* __restrict__ b2) {
    if (blockIdx.x < VPREP_CTAS) {
        int idx = blockIdx.x * blockDim.x + threadIdx.x;
        if (idx >= NT8 * 32) return;
        int tile = idx >> 5, lane = idx & 31;
        int g = lane >> 2, t = lane & 3;
        const float* r = V + (size_t)(tile * 8 + g) * REC;
        uint2 b;
        b.x = pk2(r[2 * t],     r[2 * t + 1]);
        b.y = pk2(r[2 * t + 8], r[2 * t + 9]);
        g_Vmma[idx] = b;
    } else {
        int idx = (blockIdx.x - VPREP_CTAS) * blockDim.x + threadIdx.x;
        if (idx < SEQ * BATCH) g_sumexp[idx] = 0.0f;
        if (idx < SEQ) g_done[idx] = 0;
        if (idx >= SEQ * BATCH * REC) return;
        int r  = idx & (REC - 1);
        int sb = idx >> 4;
        int t  = tok[sb];
        const float4* e = (const float4*)(emb + (size_t)t * EMB);
        const float4* u = (const float4*)(U + (size_t)r * EMB);
        float acc = b1[r] + b2[r];
#pragma unroll
        for (int q = 0; q < EMB / 4; q++) {
            float4 ev = e[q], uv = u[q];
            acc = fmaf(ev.x, uv.x, acc);
            acc = fmaf(ev.y, uv.y, acc);
            acc = fmaf(ev.z, uv.z, acc);
            acc = fmaf(ev.w, uv.w, acc);
        }
        g_iproj[idx] = acc;
    }
}

// ---------------------------------------------------------------------------
// Kernel 2: recurrence, barrier-free. 512 threads = 16 warps; warp w owns
// batches {2w, 2w+1}; lane = 16*(b&1) + r. h exchange via 16-wide shuffles.
// ---------------------------------------------------------------------------
__global__ void __launch_bounds__(512) rnn_kernel(const float* __restrict__ W,
                                                  const float* __restrict__ h0) {
    const int tid  = threadIdx.x;
    const int w    = tid >> 5, lane = tid & 31;
    const int r    = lane & 15;
    const int base = 32 * w + lane;           // == b*16 + r

    float wreg[REC];
    {
        const float4* wr = (const float4*)(W + r * REC);
        float4 a = wr[0], b = wr[1], c = wr[2], d = wr[3];
        wreg[0]=a.x; wreg[1]=a.y; wreg[2]=a.z; wreg[3]=a.w;
        wreg[4]=b.x; wreg[5]=b.y; wreg[6]=b.z; wreg[7]=b.w;
        wreg[8]=c.x; wreg[9]=c.y; wreg[10]=c.z; wreg[11]=c.w;
        wreg[12]=d.x; wreg[13]=d.y; wreg[14]=d.z; wreg[15]=d.w;
    }

    float c0 = h0[r];

    float ip[2];
    ip[0] = g_iproj[base];
    ip[1] = g_iproj[512 + base];

    for (int t = 0; t < SEQ; t++) {
        g_hidden[t * 512 + base] = c0;
        if (t < SEQ - 1) {
            float acc0 = ip[t & 1], acc1 = 0.f;
            if (t + 2 < SEQ) ip[t & 1] = g_iproj[(t + 2) * 512 + base];
#pragma unroll
            for (int j = 0; j < 8; j++) {
                float hj0 = __shfl_sync(0xffffffffu, c0, j, 16);
                float hj1 = __shfl_sync(0xffffffffu, c0, j + 8, 16);
                acc0 = fmaf(wreg[j], hj0, acc0);
                acc1 = fmaf(wreg[j + 8], hj1, acc1);
            }
            float x = acc0 + acc1;
            float e = __expf(2.0f * x);
            c0 = 1.0f - __fdividef(2.0f, e + 1.0f);
        }
    }
}

// Build A fragments (h, batch-as-M): 2 m-tiles (batch 0-15, 16-31).
__device__ __forceinline__ void make_afrags(uint32_t a[2][4], int s, int g, int t) {
    const float* hb = g_hidden + s * 512;
#pragma unroll
    for (int m = 0; m < 2; m++) {
        int r0 = m * 16 + g, r1 = m * 16 + g + 8;
        float2 x0 = *(const float2*)(hb + r0 * REC + 2 * t);
        float2 x1 = *(const float2*)(hb + r1 * REC + 2 * t);
        float2 x2 = *(const float2*)(hb + r0 * REC + 2 * t + 8);
        float2 x3 = *(const float2*)(hb + r1 * REC + 2 * t + 8);
        a[m][0] = pk2(x0.x, x0.y);
        a[m][1] = pk2(x1.x, x1.y);
        a[m][2] = pk2(x2.x, x2.y);
        a[m][3] = pk2(x3.x, x3.y);
    }
}

// ---------------------------------------------------------------------------
// Kernel 3 (FUSED, R12 bid layout — all A bids before all B bids):
//   [0, TOTAL_A):        sumexp role; signals g_done[s].
//   [TOTAL_A, +TOTAL_B): write role; short spin (producers mostly retired).
// ---------------------------------------------------------------------------
__global__ void __launch_bounds__(256) fused_kernel(float* __restrict__ out) {
    __shared__ float buf[8][32][36];
    const int bid = blockIdx.x;
    const int tid = threadIdx.x;
    const int wid = tid >> 5, lane = tid & 31;
    const int g = lane >> 2, t = lane & 3;

    if (bid < TOTAL_A) {
        // ---------------- sumexp role ----------------
        const int slice = bid % SLICES_A;
        const int s     = bid / SLICES_A;

        uint32_t a[2][4];
        make_afrags(a, s, g, t);

        float acc[4] = {0.f, 0.f, 0.f, 0.f};
        const int tile0 = slice * TPC_A + wid * TPW_A;
        const uint2* bp = &g_Vmma[(size_t)tile0 * 32 + lane];

        for (int i = 0; i < TPW_A; i++) {
            uint2 b = bp[i * 32];
            float d0[4] = {0.f, 0.f, 0.f, 0.f};
            float d1[4] = {0.f, 0.f, 0.f, 0.f};
            mma16816(d0, a[0], b.x, b.y);
            mma16816(d1, a[1], b.x, b.y);
            acc[0] += __expf(d0[0]) + __expf(d0[1]);
            acc[1] += __expf(d0[2]) + __expf(d0[3]);
            acc[2] += __expf(d1[0]) + __expf(d1[1]);
            acc[3] += __expf(d1[2]) + __expf(d1[3]);
        }

#pragma unroll
        for (int k = 0; k < 4; k++) {
            float v = acc[k];
            v += __shfl_xor_sync(0xffffffffu, v, 1);
            v += __shfl_xor_sync(0xffffffffu, v, 2);
            acc[k] = v;
        }

        float (*red)[BATCH] = (float (*)[BATCH])buf;   // alias staging smem
        if (t == 0) {
            red[wid][g]      = acc[0];
            red[wid][g + 8]  = acc[1];
            red[wid][g + 16] = acc[2];
            red[wid][g + 24] = acc[3];
        }
        __syncthreads();
        if (tid < BATCH) {
            float tot = 0.f;
#pragma unroll
            for (int w = 0; w < 8; w++) tot += red[w][tid];
            atomicAdd(&g_sumexp[s * BATCH + tid], tot);
        }
        __syncthreads();
        if (tid == 0) {
            __threadfence();
            atomicAdd(&g_done[s], 1);
        }
    } else {
        // ---------------- write role ----------------
        const int j     = bid - TOTAL_A;
        const int slice = j % SLICES_B;
        const int s     = j / SLICES_B;

        uint32_t a[2][4];
        make_afrags(a, s, g, t);

        if (tid == 0) {
            while (atomicAdd(&g_done[s], 0) < SLICES_A) __nanosleep(256);
        }
        __syncthreads();
        __threadfence();

        const float* se = g_sumexp + s * BATCH;
        const float nz0 = -__logf(se[g]);
        const float nz1 = -__logf(se[g + 8]);
        const float nz2 = -__logf(se[g + 16]);
        const float nz3 = -__logf(se[g + 24]);

        float* obase = out + (size_t)s * BATCH * VOCAB;
        float (*wb)[36] = buf[wid];

        const int rrow = lane >> 3;          // readout row-in-group 0..3
        const int rcol = (lane & 7) * 4;     // readout col 0..28

        for (int i = 0; i < CPW_B; i++) {
            const int chunk = slice * CPC_B + i * 8 + wid;
            const int v0 = chunk * 32;

#pragma unroll
            for (int jj = 0; jj < 4; jj++) {
                uint2 b = g_Vmma[(size_t)(chunk * 4 + jj) * 32 + lane];
                float d0[4] = {nz0, nz0, nz1, nz1};
                float d1[4] = {nz2, nz2, nz3, nz3};
                mma16816(d0, a[0], b.x, b.y);
                mma16816(d1, a[1], b.x, b.y);
                const int col = jj * 8 + 2 * t;
                *(float2*)&wb[g][col]      = make_float2(d0[0], d0[1]);
                *(float2*)&wb[g + 8][col]  = make_float2(d0[2], d0[3]);
                *(float2*)&wb[g + 16][col] = make_float2(d1[0], d1[1]);
                *(float2*)&wb[g + 24][col] = make_float2(d1[2], d1[3]);
            }
            __syncwarp();

#pragma unroll
            for (int it = 0; it < 8; it++) {
                const int row = it * 4 + rrow;
                float4 x = *(float4*)&wb[row][rcol];
                *(float4*)(obase + (size_t)row * VOCAB + v0 + rcol) = x;
            }
            __syncwarp();
        }
    }
}

// ---------------------------------------------------------------------------
extern "C" void kernel_launch(void* const* d_in, const int* in_sizes, int n_in,
                              void* d_out, int out_size) {
    const int*   tok = (const int*)  d_in[0];
    const float* emb = (const float*)d_in[1];
    const float* U   = (const float*)d_in[2];
    const float* W   = (const float*)d_in[3];
    const float* V   = (const float*)d_in[4];
    const float* b1  = (const float*)d_in[5];
    const float* b2  = (const float*)d_in[6];
    const float* h0  = (const float*)d_in[7];
    float* out = (float*)d_out;

    prep_kernel<<<VPREP_CTAS + IPROJ_CTAS, 256>>>(V, tok, emb, U, b1, b2);
    rnn_kernel<<<1, 512>>>(W, h0);
    fused_kernel<<<TOTAL_A + TOTAL_B, 256>>>(out);
}